// round 15
// baseline (speedup 1.0000x reference)
#include <cuda_runtime.h>
#include <cuda_fp16.h>
#include <cstdint>

#define NB   8
#define ND   1024
#define DD   100
#define NV   30000
#define NC   512

#define K1   112              // 100 + 12 zero pad (7 x k16)
#define NVP  30208            // 118 * 256
#define TILE_N 256
#define TILE_M 64
#define N_VT (NVP / TILE_N)   // 118
#define NDC  4                // 4 chunks of 64 rows = 256 rows per CTA

#define PITCH 240             // 15 x 16B, odd units -> conflict-free ldmatrix
#define ABUF  (TILE_M * PITCH)               // 15360
#define BBUF  (TILE_N * PITCH)               // 61440
#define NSTAGE 3
#define VRED_OFF  (BBUF + NSTAGE * ABUF)             // 107520
#define MBAR_OFF  (VRED_OFF + 8 * 64 * 4)            // 109568 (ready[3], free[3])
#define SMEM_MAIN (MBAR_OFF + 64)                    // 109632

#define INV_STEP (14.0f / 1.49f)

// -------- device scratch --------
__device__ __half g_A[(size_t)NB * ND * K1];     // [row][k] row-major, 224B rows
__device__ __half g_B[(size_t)NVP * K1];         // [v][k]
__device__ float g_weighted[32 * NVP];           // row = mc*8 + b  (mc in 0..3)
__device__ float g_w8[8 * NVP];                  // folded over mc
__device__ float g_binw[16];
__device__ float g_part[2 * 128 * 36];

// -------- helpers --------
__device__ __forceinline__ uint32_t smem_u32(const void* p) {
    return (uint32_t)__cvta_generic_to_shared(p);
}
__device__ __forceinline__ void cpa16(uint32_t dst, const void* src) {
    asm volatile("cp.async.cg.shared.global [%0], [%1], 16;" :: "r"(dst), "l"(src));
}
__device__ __forceinline__ void cpa_mbar_arrive_noinc(uint32_t mbar) {
    asm volatile("cp.async.mbarrier.arrive.noinc.shared.b64 [%0];" :: "r"(mbar) : "memory");
}
__device__ __forceinline__ void mbar_init(uint32_t mbar, uint32_t cnt) {
    asm volatile("mbarrier.init.shared.b64 [%0], %1;" :: "r"(mbar), "r"(cnt) : "memory");
}
__device__ __forceinline__ void mbar_arrive(uint32_t mbar) {
    asm volatile("mbarrier.arrive.shared.b64 _, [%0];" :: "r"(mbar) : "memory");
}
__device__ __forceinline__ void mbar_wait(uint32_t mbar, uint32_t parity) {
    asm volatile(
        "{\n\t.reg .pred P1;\n\t"
        "WAIT_%=:\n\t"
        "mbarrier.try_wait.parity.acquire.cta.shared::cta.b64 P1, [%0], %1, 0x989680;\n\t"
        "@P1 bra.uni DONE_%=;\n\t"
        "bra.uni WAIT_%=;\n\t"
        "DONE_%=:\n\t}"
        :: "r"(mbar), "r"(parity) : "memory");
}

__device__ __forceinline__ void ldm4(uint32_t& r0, uint32_t& r1, uint32_t& r2, uint32_t& r3,
                                     uint32_t addr) {
    asm volatile("ldmatrix.sync.aligned.m8n8.x4.shared.b16 {%0,%1,%2,%3}, [%4];"
                 : "=r"(r0), "=r"(r1), "=r"(r2), "=r"(r3) : "r"(addr));
}
// f16 x f16 inputs -> f32 accumulators
__device__ __forceinline__ void mma16816(float* c, const uint32_t* a, const uint32_t* b) {
    asm volatile(
        "mma.sync.aligned.m16n8k16.row.col.f32.f16.f16.f32 "
        "{%0,%1,%2,%3}, {%4,%5,%6,%7}, {%8,%9}, {%0,%1,%2,%3};"
        : "+f"(c[0]), "+f"(c[1]), "+f"(c[2]), "+f"(c[3])
        : "r"(a[0]), "r"(a[1]), "r"(a[2]), "r"(a[3]), "r"(b[0]), "r"(b[1]));
}
// init form: c = zero register (kills per-dc accumulator-zeroing MOVs)
__device__ __forceinline__ void mma16816_init(float* d, const uint32_t* a, const uint32_t* b,
                                              float z) {
    asm volatile(
        "mma.sync.aligned.m16n8k16.row.col.f32.f16.f16.f32 "
        "{%0,%1,%2,%3}, {%4,%5,%6,%7}, {%8,%9}, {%10,%10,%10,%10};"
        : "=f"(d[0]), "=f"(d[1]), "=f"(d[2]), "=f"(d[3])
        : "r"(a[0]), "r"(a[1]), "r"(a[2]), "r"(a[3]), "r"(b[0]), "r"(b[1]), "f"(z));
}
__device__ __forceinline__ float fma_sat(float a, float b, float c) {
    float d;
    asm("fma.rn.sat.f32 %0, %1, %2, %3;" : "=f"(d) : "f"(a), "f"(b), "f"(c));
    return d;
}
// shfl.idx taking raw bits as lane index (b[4:0] used; magic guarantees low bits = dig)
__device__ __forceinline__ float shfl_idx_raw(float v, uint32_t idx) {
    float r;
    asm volatile("shfl.sync.idx.b32 %0, %1, %2, 0x1f, 0xffffffff;"
                 : "=f"(r) : "f"(v), "r"(idx));
    return r;
}

// -------- kernel 1: gather + f16 cast of A rows (+ bin weights in block 0) --------
__global__ void k_prepA(const int* __restrict__ doc_index, const float* __restrict__ emb,
                        const float* __restrict__ diff, const float* __restrict__ start) {
    if (blockIdx.x == 0 && threadIdx.x == 0) {
        float acc = start[0];
        for (int j = 0; j < 16; j++) {
            float d = diff[j];
            acc += d > 0.f ? d : 0.f;
            g_binw[j] = acc;
        }
    }
    int e = blockIdx.x * blockDim.x + threadIdx.x;
    if (e >= NB * ND * K1) return;
    int r = e / K1;
    int k = e - r * K1;
    float val = (k < DD) ? emb[(size_t)doc_index[r] * DD + k] : 0.f;
    g_A[e] = __float2half(val);
}

// -------- kernel 2: transpose + f16 cast of B --------
__global__ void k_prepB(const float* __restrict__ Vv_T) {
    __shared__ __half stage[128 * 120];
    const int tid = threadIdx.x;
    const int v0 = blockIdx.x * 128;

    for (int idx = tid; idx < DD * 128; idx += 256) {
        int k = idx >> 7, c = idx & 127;
        int v = v0 + c;
        float val = (v < NV) ? Vv_T[(size_t)k * NV + v] : 0.f;
        stage[c * 120 + k] = __float2half(val);
    }
    for (int idx = tid; idx < 128 * 12; idx += 256) {
        int c = idx / 12, u = idx - c * 12;
        stage[c * 120 + DD + u] = __float2half(0.f);
    }
    __syncthreads();
    const uint32_t* sg = (const uint32_t*)stage;
    uint32_t* dst = (uint32_t*)g_B;
    for (int e = tid; e < 128 * 56; e += 256) {
        int row = e / 56, u = e - row * 56;
        dst[(size_t)(v0 + row) * 56 + u] = sg[row * 60 + u];
    }
}

// -------- kernel 3: f16-input tensor GEMM + digitize + attn-weighted d-reduction --------
// grid (118, 32): blockIdx.y = b*4 + mc; 256 threads = 8 warps 2(M) x 4(N); warp tile 32x64.
// 2 CTAs / SM; 3-stage A ring with noinc-mbarrier producer/consumer.  [converged design]
__device__ __forceinline__ void load_a_chunk(int rowbase, int dc, uint32_t dbase, int tid) {
    const char* base = (const char*)g_A + ((size_t)(rowbase + dc * TILE_M)) * (K1 * 2);
#pragma unroll 1
    for (int i = tid; i < TILE_M * 14; i += 256) {
        int row = i / 14, u = i - row * 14;
        cpa16(dbase + row * PITCH + u * 16, base + (size_t)row * (K1 * 2) + u * 16);
    }
}

__global__ void __launch_bounds__(256, 2)
k_main(const float* __restrict__ attn) {
    extern __shared__ unsigned char sm[];
    const uint32_t sBs = smem_u32(sm);
    const uint32_t sAs = sBs + BBUF;
    float* vred = (float*)(sm + VRED_OFF);
    const uint32_t mb_ready = sBs + MBAR_OFF;        // 3 x 8B
    const uint32_t mb_free  = sBs + MBAR_OFF + 24;   // 3 x 8B

    const int tid  = threadIdx.x;
    const int lane = tid & 31, wid = tid >> 5;
    const int wm   = wid >> 2, wn = wid & 3;      // 2 x 4 warps
    const int by   = blockIdx.y;
    const int b    = by >> 2;
    const int mc   = by & 3;
    const int rowbase = b * ND + mc * 256;
    const int v0   = blockIdx.x * TILE_N;

    const float binw_r = __ldg(&g_binw[lane & 15]);
    const int lm_row  = lane & 15;
    const int lm_koff = (lane >> 4) << 3;

    // digitize: y = sat(s*S2 + C2), m = rn(y*15 + 2^23), bits[4:0] = dig
    const float S2 = INV_STEP / 15.0f;
    const float C2 = (0.5f * INV_STEP + 0.5f) / 15.0f;
    const float MAGIC = 8388608.0f;   // 2^23
    const float FZERO = 0.0f;

    // ---- init mbarriers, then make visible ----
    if (tid == 0) {
#pragma unroll
        for (int s = 0; s < 3; s++) {
            mbar_init(mb_ready + s * 8, 256);
            mbar_init(mb_free  + s * 8, 8);
        }
    }
    __syncthreads();

    // ---- prologue: B + A0 -> ready[0]; A1 -> ready[1] ----
    {
        const char* bsrc = (const char*)g_B + (size_t)v0 * (K1 * 2);
#pragma unroll 1
        for (int i = tid; i < TILE_N * 14; i += 256) {
            int row = i / 14, u = i - row * 14;
            cpa16(sBs + row * PITCH + u * 16, bsrc + (size_t)row * (K1 * 2) + u * 16);
        }
        load_a_chunk(rowbase, 0, sAs, tid);
        cpa_mbar_arrive_noinc(mb_ready + 0 * 8);     // B + A0 tracked
        load_a_chunk(rowbase, 1, sAs + ABUF, tid);
        cpa_mbar_arrive_noinc(mb_ready + 1 * 8);
    }

    float vcol[16];
#pragma unroll
    for (int j = 0; j < 16; j++) vcol[j] = 0.f;

    const float* attn_b = attn + rowbase;

#pragma unroll 1
    for (int dc = 0; dc < NDC; ++dc) {
        const int slot = dc % NSTAGE;

        // 1. wait A[dc] (and B, folded into ready[0]) ready
        mbar_wait(mb_ready + slot * 8, (uint32_t)((dc / 3) & 1));

        // 2. prefetch A[dc+2] into slot (dc+2)%3 (wait for its readers first)
        if (dc + 2 < NDC) {
            const int ps = (dc + 2) % NSTAGE;
            if (dc >= 1)
                mbar_wait(mb_free + ps * 8, (uint32_t)(((dc - 1) / 3) & 1));
            load_a_chunk(rowbase, dc + 2, sAs + (uint32_t)ps * ABUF, tid);
            cpa_mbar_arrive_noinc(mb_ready + ps * 8);
        }

        const uint32_t sA = sAs + (uint32_t)slot * ABUF;

        // prefetch the 4 attn values used in this dc's epilogue
        const int arow = dc * TILE_M + wm * 32 + (lane >> 2);
        float av[2][2];
#pragma unroll
        for (int mi = 0; mi < 2; mi++)
#pragma unroll
            for (int gg = 0; gg < 2; gg++)
                av[mi][gg] = __ldg(&attn_b[arow + mi * 16 + gg * 8]);

        float acc[2][8][4];

        // ---- 3. 7 x k16 MMA steps (ks=0 uses zero-input form: no acc zeroing) ----
#pragma unroll
        for (int ks = 0; ks < K1 / 16; ks++) {
            const int kl = ks * 16;
            uint32_t a[2][4];
#pragma unroll
            for (int mi = 0; mi < 2; mi++) {
                uint32_t addr = sA + (wm * 32 + mi * 16 + lm_row) * PITCH
                              + (kl + lm_koff) * 2;
                ldm4(a[mi][0], a[mi][1], a[mi][2], a[mi][3], addr);
            }
            uint32_t bf[8][2];
#pragma unroll
            for (int nb = 0; nb < 4; nb++) {
                uint32_t addr = sBs + (wn * 64 + nb * 16 + lm_row) * PITCH
                              + (kl + lm_koff) * 2;
                uint32_t r0, r1, r2, r3;
                ldm4(r0, r1, r2, r3, addr);
                bf[nb * 2][0] = r0;     bf[nb * 2][1] = r2;
                bf[nb * 2 + 1][0] = r1; bf[nb * 2 + 1][1] = r3;
            }
            if (ks == 0) {
#pragma unroll
                for (int mi = 0; mi < 2; mi++)
#pragma unroll
                    for (int nj = 0; nj < 8; nj++)
                        mma16816_init(acc[mi][nj], a[mi], bf[nj], FZERO);
            } else {
#pragma unroll
                for (int mi = 0; mi < 2; mi++)
#pragma unroll
                    for (int nj = 0; nj < 8; nj++)
                        mma16816(acc[mi][nj], a[mi], bf[nj]);
            }
        }

        // 4. this warp is done reading A stage 'slot'
        if (lane == 0) mbar_arrive(mb_free + slot * 8);

        // ---- 5. epilogue: sat-fma, magic-fma, shfl(raw), fma ----
#pragma unroll
        for (int mi = 0; mi < 2; mi++) {
#pragma unroll
            for (int gg = 0; gg < 2; gg++) {
                const float a_v = av[mi][gg];
#pragma unroll
                for (int nj = 0; nj < 8; nj++) {
#pragma unroll
                    for (int cc = 0; cc < 2; cc++) {
                        float s = acc[mi][nj][gg * 2 + cc];
                        float y = fma_sat(s, S2, C2);
                        float m = fmaf(y, 15.0f, MAGIC);
                        float w = shfl_idx_raw(binw_r, __float_as_uint(m));
                        vcol[nj * 2 + cc] = fmaf(a_v, w, vcol[nj * 2 + cc]);
                    }
                }
            }
        }
    }

    // ---- reduce vcol over lanes sharing the same columns ----
#pragma unroll
    for (int j = 0; j < 16; j++) {
        vcol[j] += __shfl_down_sync(0xffffffffu, vcol[j], 16);
        vcol[j] += __shfl_down_sync(0xffffffffu, vcol[j], 8);
        vcol[j] += __shfl_down_sync(0xffffffffu, vcol[j], 4);
    }
    if (lane < 4) {
#pragma unroll
        for (int j = 0; j < 16; j++) {
            int nj = j >> 1, cc = j & 1;
            vred[wid * 64 + nj * 8 + lane * 2 + cc] = vcol[j];
        }
    }
    __syncthreads();
    {
        int wn2 = tid >> 6, cl = tid & 63;
        float s = vred[wn2 * 64 + cl] + vred[(4 + wn2) * 64 + cl];
        g_weighted[(size_t)(mc * 8 + b) * NVP + v0 + tid] = s;
    }
}

// -------- kernel 3b: fold mc quarters: g_w8[b][v] = sum_mc g_weighted --------
__global__ void __launch_bounds__(256)
k_fold() {
    int e = blockIdx.x * blockDim.x + threadIdx.x;
    if (e >= 8 * NVP) return;
    g_w8[e] = (g_weighted[e] + g_weighted[8 * NVP + e])
            + (g_weighted[16 * NVP + e] + g_weighted[24 * NVP + e]);
}

// -------- kernel 4a: phi L1 + partial dots; 4 rows/block, 2 NV-chunks, 3 CTAs/SM --------
// grid (128 rb, 2 sp): ~14.8 main-loop iterations per block.
#define CHV 15104   // NVP/2
__global__ void __launch_bounds__(256, 3)
k_fin1(const float* __restrict__ phi) {
    const int rb  = blockIdx.x;          // 0..127 (4 concept rows each)
    const int sp  = blockIdx.y;          // 0..1   (NV chunk)
    const int n0  = rb * 4;
    const int tid = threadIdx.x;

    const int vbeg = sp * CHV;
    const int vend = (vbeg + CHV < NV) ? vbeg + CHV : NV;

    float acc[4][8];
    float l1[4];
#pragma unroll
    for (int r = 0; r < 4; r++) {
        l1[r] = 0.f;
#pragma unroll
        for (int bb = 0; bb < 8; bb++) acc[r][bb] = 0.f;
    }

    for (int base = vbeg + tid * 4; base < vend; base += 1024) {
        float4 w[8];
#pragma unroll
        for (int bb = 0; bb < 8; bb++)
            w[bb] = *(const float4*)&g_w8[(size_t)bb * NVP + base];
#pragma unroll
        for (int r = 0; r < 4; r++) {
            float4 p = *(const float4*)&phi[(size_t)(n0 + r) * NV + base];
            l1[r] += fabsf(p.x) + fabsf(p.y) + fabsf(p.z) + fabsf(p.w);
#pragma unroll
            for (int bb = 0; bb < 8; bb++)
                acc[r][bb] += p.x * w[bb].x + p.y * w[bb].y + p.z * w[bb].z + p.w * w[bb].w;
        }
    }

    const unsigned mask = 0xffffffffu;
#pragma unroll
    for (int r = 0; r < 4; r++) {
#pragma unroll
        for (int bb = 0; bb < 8; bb++)
#pragma unroll
            for (int o = 16; o > 0; o >>= 1)
                acc[r][bb] += __shfl_down_sync(mask, acc[r][bb], o);
#pragma unroll
        for (int o = 16; o > 0; o >>= 1)
            l1[r] += __shfl_down_sync(mask, l1[r], o);
    }

    __shared__ float red[8][36];
    const int wid = tid >> 5, lane = tid & 31;
    if (lane == 0) {
#pragma unroll
        for (int r = 0; r < 4; r++) {
#pragma unroll
            for (int bb = 0; bb < 8; bb++) red[wid][r * 9 + bb] = acc[r][bb];
            red[wid][r * 9 + 8] = l1[r];
        }
    }
    __syncthreads();
    if (tid < 36) {
        float s = 0.f;
#pragma unroll
        for (int w8 = 0; w8 < 8; w8++) s += red[w8][tid];
        g_part[(sp * 128 + rb) * 36 + tid] = s;
    }
}

// -------- kernel 4b: combine partials + normalize + write output --------
__global__ void __launch_bounds__(64)
k_fin2(float* __restrict__ out) {
    const int rb  = blockIdx.x;          // 0..127
    const int tid = threadIdx.x;
    __shared__ float tot[36];
    if (tid < 36) {
        float s = g_part[rb * 36 + tid] + g_part[(128 + rb) * 36 + tid];
        tot[tid] = s;
    }
    __syncthreads();
    if (tid < 32) {
        int r  = tid >> 3;
        int bb = tid & 7;
        float l = tot[r * 9 + 8];
        out[bb * NC + (rb * 4 + r)] = tot[r * 9 + bb] / fmaxf(l, 1e-12f);
    }
}

// -------- launcher --------
extern "C" void kernel_launch(void* const* d_in, const int* in_sizes, int n_in,
                              void* d_out, int out_size) {
    const int*   doc_index = (const int*)d_in[0];
    const float* attn      = (const float*)d_in[1];
    const float* emb       = (const float*)d_in[2];
    const float* vvt       = (const float*)d_in[3];
    const float* phi       = (const float*)d_in[4];
    const float* diff      = (const float*)d_in[5];
    const float* start     = (const float*)d_in[6];
    float* out = (float*)d_out;

    k_prepA<<<(NB * ND * K1 + 511) / 512, 512>>>(doc_index, emb, diff, start);
    k_prepB<<<NVP / 128, 256>>>(vvt);

    cudaFuncSetAttribute(k_main, cudaFuncAttributeMaxDynamicSharedMemorySize, SMEM_MAIN);
    dim3 grid(N_VT, NB * 4);
    k_main<<<grid, 256, SMEM_MAIN>>>(attn);

    k_fold<<<(8 * NVP + 255) / 256, 256>>>();

    dim3 g1(128, 2);
    k_fin1<<<g1, 256>>>(phi);
    k_fin2<<<128, 64>>>(out);
}

// round 16
// speedup vs baseline: 1.0228x; 1.0228x over previous
#include <cuda_runtime.h>
#include <cuda_fp16.h>
#include <cstdint>

#define NB   8
#define ND   1024
#define DD   100
#define NV   30000
#define NC   512

#define K1   112              // 100 + 12 zero pad (7 x k16)
#define NVP  30208            // 118 * 256
#define TILE_N 256
#define TILE_M 64
#define N_VT (NVP / TILE_N)   // 118
#define NDC  4                // 4 chunks of 64 rows = 256 rows per CTA

#define PITCH 240             // 15 x 16B, odd units -> conflict-free ldmatrix
#define ABUF  (TILE_M * PITCH)               // 15360
#define BBUF  (TILE_N * PITCH)               // 61440
#define NSTAGE 3
#define VRED_OFF  (BBUF + NSTAGE * ABUF)             // 107520
#define MBAR_OFF  (VRED_OFF + 8 * 64 * 4)            // 109568 (ready[3], free[3])
#define SMEM_MAIN (MBAR_OFF + 64)                    // 109632

#define INV_STEP (14.0f / 1.49f)

// -------- device scratch --------
__device__ __half g_A[(size_t)NB * ND * K1];     // [row][k] row-major, 224B rows
__device__ __half g_B[(size_t)NVP * K1];         // [v][k]
__device__ float g_weighted[32 * NVP];           // row = mc*8 + b  (mc in 0..3)
__device__ float g_w8[8 * NVP];                  // folded over mc
__device__ float g_binw[16];
__device__ float g_part[4 * 128 * 36];

// -------- helpers --------
__device__ __forceinline__ uint32_t smem_u32(const void* p) {
    return (uint32_t)__cvta_generic_to_shared(p);
}
__device__ __forceinline__ void cpa16(uint32_t dst, const void* src) {
    asm volatile("cp.async.cg.shared.global [%0], [%1], 16;" :: "r"(dst), "l"(src));
}
__device__ __forceinline__ void cpa_mbar_arrive_noinc(uint32_t mbar) {
    asm volatile("cp.async.mbarrier.arrive.noinc.shared.b64 [%0];" :: "r"(mbar) : "memory");
}
__device__ __forceinline__ void mbar_init(uint32_t mbar, uint32_t cnt) {
    asm volatile("mbarrier.init.shared.b64 [%0], %1;" :: "r"(mbar), "r"(cnt) : "memory");
}
__device__ __forceinline__ void mbar_arrive(uint32_t mbar) {
    asm volatile("mbarrier.arrive.shared.b64 _, [%0];" :: "r"(mbar) : "memory");
}
__device__ __forceinline__ void mbar_wait(uint32_t mbar, uint32_t parity) {
    asm volatile(
        "{\n\t.reg .pred P1;\n\t"
        "WAIT_%=:\n\t"
        "mbarrier.try_wait.parity.acquire.cta.shared::cta.b64 P1, [%0], %1, 0x989680;\n\t"
        "@P1 bra.uni DONE_%=;\n\t"
        "bra.uni WAIT_%=;\n\t"
        "DONE_%=:\n\t}"
        :: "r"(mbar), "r"(parity) : "memory");
}

__device__ __forceinline__ void ldm4(uint32_t& r0, uint32_t& r1, uint32_t& r2, uint32_t& r3,
                                     uint32_t addr) {
    asm volatile("ldmatrix.sync.aligned.m8n8.x4.shared.b16 {%0,%1,%2,%3}, [%4];"
                 : "=r"(r0), "=r"(r1), "=r"(r2), "=r"(r3) : "r"(addr));
}
// f16 x f16 inputs -> f32 accumulators
__device__ __forceinline__ void mma16816(float* c, const uint32_t* a, const uint32_t* b) {
    asm volatile(
        "mma.sync.aligned.m16n8k16.row.col.f32.f16.f16.f32 "
        "{%0,%1,%2,%3}, {%4,%5,%6,%7}, {%8,%9}, {%0,%1,%2,%3};"
        : "+f"(c[0]), "+f"(c[1]), "+f"(c[2]), "+f"(c[3])
        : "r"(a[0]), "r"(a[1]), "r"(a[2]), "r"(a[3]), "r"(b[0]), "r"(b[1]));
}
// init form: c = zero register (kills per-dc accumulator-zeroing MOVs)
__device__ __forceinline__ void mma16816_init(float* d, const uint32_t* a, const uint32_t* b,
                                              float z) {
    asm volatile(
        "mma.sync.aligned.m16n8k16.row.col.f32.f16.f16.f32 "
        "{%0,%1,%2,%3}, {%4,%5,%6,%7}, {%8,%9}, {%10,%10,%10,%10};"
        : "=f"(d[0]), "=f"(d[1]), "=f"(d[2]), "=f"(d[3])
        : "r"(a[0]), "r"(a[1]), "r"(a[2]), "r"(a[3]), "r"(b[0]), "r"(b[1]), "f"(z));
}
__device__ __forceinline__ float fma_sat(float a, float b, float c) {
    float d;
    asm("fma.rn.sat.f32 %0, %1, %2, %3;" : "=f"(d) : "f"(a), "f"(b), "f"(c));
    return d;
}
// shfl.idx taking raw bits as lane index (b[4:0] used; magic guarantees low bits = dig)
__device__ __forceinline__ float shfl_idx_raw(float v, uint32_t idx) {
    float r;
    asm volatile("shfl.sync.idx.b32 %0, %1, %2, 0x1f, 0xffffffff;"
                 : "=f"(r) : "f"(v), "r"(idx));
    return r;
}

// -------- kernel 1: gather + f16 cast of A rows (+ bin weights in block 0) --------
__global__ void k_prepA(const int* __restrict__ doc_index, const float* __restrict__ emb,
                        const float* __restrict__ diff, const float* __restrict__ start) {
    if (blockIdx.x == 0 && threadIdx.x == 0) {
        float acc = start[0];
        for (int j = 0; j < 16; j++) {
            float d = diff[j];
            acc += d > 0.f ? d : 0.f;
            g_binw[j] = acc;
        }
    }
    int e = blockIdx.x * blockDim.x + threadIdx.x;
    if (e >= NB * ND * K1) return;
    int r = e / K1;
    int k = e - r * K1;
    float val = (k < DD) ? emb[(size_t)doc_index[r] * DD + k] : 0.f;
    g_A[e] = __float2half(val);
}

// -------- kernel 2: transpose + f16 cast of B --------
__global__ void k_prepB(const float* __restrict__ Vv_T) {
    __shared__ __half stage[128 * 120];
    const int tid = threadIdx.x;
    const int v0 = blockIdx.x * 128;

    for (int idx = tid; idx < DD * 128; idx += 256) {
        int k = idx >> 7, c = idx & 127;
        int v = v0 + c;
        float val = (v < NV) ? Vv_T[(size_t)k * NV + v] : 0.f;
        stage[c * 120 + k] = __float2half(val);
    }
    for (int idx = tid; idx < 128 * 12; idx += 256) {
        int c = idx / 12, u = idx - c * 12;
        stage[c * 120 + DD + u] = __float2half(0.f);
    }
    __syncthreads();
    const uint32_t* sg = (const uint32_t*)stage;
    uint32_t* dst = (uint32_t*)g_B;
    for (int e = tid; e < 128 * 56; e += 256) {
        int row = e / 56, u = e - row * 56;
        dst[(size_t)(v0 + row) * 56 + u] = sg[row * 60 + u];
    }
}

// -------- kernel 3: f16-input tensor GEMM + digitize + attn-weighted d-reduction --------
// grid (118, 32): blockIdx.y = b*4 + mc; 256 threads = 8 warps 2(M) x 4(N); warp tile 32x64.
// 2 CTAs / SM; 3-stage A ring with noinc-mbarrier producer/consumer.  [converged design]
__device__ __forceinline__ void load_a_chunk(int rowbase, int dc, uint32_t dbase, int tid) {
    const char* base = (const char*)g_A + ((size_t)(rowbase + dc * TILE_M)) * (K1 * 2);
#pragma unroll 1
    for (int i = tid; i < TILE_M * 14; i += 256) {
        int row = i / 14, u = i - row * 14;
        cpa16(dbase + row * PITCH + u * 16, base + (size_t)row * (K1 * 2) + u * 16);
    }
}

__global__ void __launch_bounds__(256, 2)
k_main(const float* __restrict__ attn) {
    extern __shared__ unsigned char sm[];
    const uint32_t sBs = smem_u32(sm);
    const uint32_t sAs = sBs + BBUF;
    float* vred = (float*)(sm + VRED_OFF);
    const uint32_t mb_ready = sBs + MBAR_OFF;        // 3 x 8B
    const uint32_t mb_free  = sBs + MBAR_OFF + 24;   // 3 x 8B

    const int tid  = threadIdx.x;
    const int lane = tid & 31, wid = tid >> 5;
    const int wm   = wid >> 2, wn = wid & 3;      // 2 x 4 warps
    const int by   = blockIdx.y;
    const int b    = by >> 2;
    const int mc   = by & 3;
    const int rowbase = b * ND + mc * 256;
    const int v0   = blockIdx.x * TILE_N;

    const float binw_r = __ldg(&g_binw[lane & 15]);
    const int lm_row  = lane & 15;
    const int lm_koff = (lane >> 4) << 3;

    // digitize: y = sat(s*S2 + C2), m = rn(y*15 + 2^23), bits[4:0] = dig
    const float S2 = INV_STEP / 15.0f;
    const float C2 = (0.5f * INV_STEP + 0.5f) / 15.0f;
    const float MAGIC = 8388608.0f;   // 2^23
    const float FZERO = 0.0f;

    // ---- init mbarriers, then make visible ----
    if (tid == 0) {
#pragma unroll
        for (int s = 0; s < 3; s++) {
            mbar_init(mb_ready + s * 8, 256);
            mbar_init(mb_free  + s * 8, 8);
        }
    }
    __syncthreads();

    // ---- prologue: B + A0 -> ready[0]; A1 -> ready[1] ----
    {
        const char* bsrc = (const char*)g_B + (size_t)v0 * (K1 * 2);
#pragma unroll 1
        for (int i = tid; i < TILE_N * 14; i += 256) {
            int row = i / 14, u = i - row * 14;
            cpa16(sBs + row * PITCH + u * 16, bsrc + (size_t)row * (K1 * 2) + u * 16);
        }
        load_a_chunk(rowbase, 0, sAs, tid);
        cpa_mbar_arrive_noinc(mb_ready + 0 * 8);     // B + A0 tracked
        load_a_chunk(rowbase, 1, sAs + ABUF, tid);
        cpa_mbar_arrive_noinc(mb_ready + 1 * 8);
    }

    float vcol[16];
#pragma unroll
    for (int j = 0; j < 16; j++) vcol[j] = 0.f;

    const float* attn_b = attn + rowbase;

#pragma unroll 1
    for (int dc = 0; dc < NDC; ++dc) {
        const int slot = dc % NSTAGE;

        // 1. wait A[dc] (and B, folded into ready[0]) ready
        mbar_wait(mb_ready + slot * 8, (uint32_t)((dc / 3) & 1));

        // 2. prefetch A[dc+2] into slot (dc+2)%3 (wait for its readers first)
        if (dc + 2 < NDC) {
            const int ps = (dc + 2) % NSTAGE;
            if (dc >= 1)
                mbar_wait(mb_free + ps * 8, (uint32_t)(((dc - 1) / 3) & 1));
            load_a_chunk(rowbase, dc + 2, sAs + (uint32_t)ps * ABUF, tid);
            cpa_mbar_arrive_noinc(mb_ready + ps * 8);
        }

        const uint32_t sA = sAs + (uint32_t)slot * ABUF;

        // prefetch the 4 attn values used in this dc's epilogue
        const int arow = dc * TILE_M + wm * 32 + (lane >> 2);
        float av[2][2];
#pragma unroll
        for (int mi = 0; mi < 2; mi++)
#pragma unroll
            for (int gg = 0; gg < 2; gg++)
                av[mi][gg] = __ldg(&attn_b[arow + mi * 16 + gg * 8]);

        float acc[2][8][4];

        // ---- 3. 7 x k16 MMA steps (ks=0 uses zero-input form: no acc zeroing) ----
#pragma unroll
        for (int ks = 0; ks < K1 / 16; ks++) {
            const int kl = ks * 16;
            uint32_t a[2][4];
#pragma unroll
            for (int mi = 0; mi < 2; mi++) {
                uint32_t addr = sA + (wm * 32 + mi * 16 + lm_row) * PITCH
                              + (kl + lm_koff) * 2;
                ldm4(a[mi][0], a[mi][1], a[mi][2], a[mi][3], addr);
            }
            uint32_t bf[8][2];
#pragma unroll
            for (int nb = 0; nb < 4; nb++) {
                uint32_t addr = sBs + (wn * 64 + nb * 16 + lm_row) * PITCH
                              + (kl + lm_koff) * 2;
                uint32_t r0, r1, r2, r3;
                ldm4(r0, r1, r2, r3, addr);
                bf[nb * 2][0] = r0;     bf[nb * 2][1] = r2;
                bf[nb * 2 + 1][0] = r1; bf[nb * 2 + 1][1] = r3;
            }
            if (ks == 0) {
#pragma unroll
                for (int mi = 0; mi < 2; mi++)
#pragma unroll
                    for (int nj = 0; nj < 8; nj++)
                        mma16816_init(acc[mi][nj], a[mi], bf[nj], FZERO);
            } else {
#pragma unroll
                for (int mi = 0; mi < 2; mi++)
#pragma unroll
                    for (int nj = 0; nj < 8; nj++)
                        mma16816(acc[mi][nj], a[mi], bf[nj]);
            }
        }

        // 4. this warp is done reading A stage 'slot'
        if (lane == 0) mbar_arrive(mb_free + slot * 8);

        // ---- 5. epilogue: sat-fma, magic-fma, shfl(raw), fma ----
#pragma unroll
        for (int mi = 0; mi < 2; mi++) {
#pragma unroll
            for (int gg = 0; gg < 2; gg++) {
                const float a_v = av[mi][gg];
#pragma unroll
                for (int nj = 0; nj < 8; nj++) {
#pragma unroll
                    for (int cc = 0; cc < 2; cc++) {
                        float s = acc[mi][nj][gg * 2 + cc];
                        float y = fma_sat(s, S2, C2);
                        float m = fmaf(y, 15.0f, MAGIC);
                        float w = shfl_idx_raw(binw_r, __float_as_uint(m));
                        vcol[nj * 2 + cc] = fmaf(a_v, w, vcol[nj * 2 + cc]);
                    }
                }
            }
        }
    }

    // ---- reduce vcol over lanes sharing the same columns ----
#pragma unroll
    for (int j = 0; j < 16; j++) {
        vcol[j] += __shfl_down_sync(0xffffffffu, vcol[j], 16);
        vcol[j] += __shfl_down_sync(0xffffffffu, vcol[j], 8);
        vcol[j] += __shfl_down_sync(0xffffffffu, vcol[j], 4);
    }
    if (lane < 4) {
#pragma unroll
        for (int j = 0; j < 16; j++) {
            int nj = j >> 1, cc = j & 1;
            vred[wid * 64 + nj * 8 + lane * 2 + cc] = vcol[j];
        }
    }
    __syncthreads();
    {
        int wn2 = tid >> 6, cl = tid & 63;
        float s = vred[wn2 * 64 + cl] + vred[(4 + wn2) * 64 + cl];
        g_weighted[(size_t)(mc * 8 + b) * NVP + v0 + tid] = s;
    }
}

// -------- kernel 3b: fold mc quarters: g_w8[b][v] = sum_mc g_weighted --------
__global__ void __launch_bounds__(256)
k_fold() {
    int e = blockIdx.x * blockDim.x + threadIdx.x;
    if (e >= 8 * NVP) return;
    g_w8[e] = (g_weighted[e] + g_weighted[8 * NVP + e])
            + (g_weighted[16 * NVP + e] + g_weighted[24 * NVP + e]);
}

// -------- kernel 4a: phi L1 + partial dots; 4 rows/block, 4 NV-chunks, unroll-2 MLP --------
// grid (128 rb, 4 sp): ~7.4 main-loop iterations per block.
#define CHV 7552   // NVP/4
__global__ void __launch_bounds__(256)
k_fin1(const float* __restrict__ phi) {
    const int rb  = blockIdx.x;          // 0..127 (4 concept rows each)
    const int sp  = blockIdx.y;          // 0..3   (NV chunk)
    const int n0  = rb * 4;
    const int tid = threadIdx.x;

    const int vbeg = sp * CHV;
    const int vend = (vbeg + CHV < NV) ? vbeg + CHV : NV;

    float acc[4][8];
    float l1[4];
#pragma unroll
    for (int r = 0; r < 4; r++) {
        l1[r] = 0.f;
#pragma unroll
        for (int bb = 0; bb < 8; bb++) acc[r][bb] = 0.f;
    }

#pragma unroll 2
    for (int base = vbeg + tid * 4; base < vend; base += 1024) {
        float4 w[8];
#pragma unroll
        for (int bb = 0; bb < 8; bb++)
            w[bb] = *(const float4*)&g_w8[(size_t)bb * NVP + base];
#pragma unroll
        for (int r = 0; r < 4; r++) {
            float4 p = *(const float4*)&phi[(size_t)(n0 + r) * NV + base];
            l1[r] += fabsf(p.x) + fabsf(p.y) + fabsf(p.z) + fabsf(p.w);
#pragma unroll
            for (int bb = 0; bb < 8; bb++)
                acc[r][bb] += p.x * w[bb].x + p.y * w[bb].y + p.z * w[bb].z + p.w * w[bb].w;
        }
    }

    const unsigned mask = 0xffffffffu;
#pragma unroll
    for (int r = 0; r < 4; r++) {
#pragma unroll
        for (int bb = 0; bb < 8; bb++)
#pragma unroll
            for (int o = 16; o > 0; o >>= 1)
                acc[r][bb] += __shfl_down_sync(mask, acc[r][bb], o);
#pragma unroll
        for (int o = 16; o > 0; o >>= 1)
            l1[r] += __shfl_down_sync(mask, l1[r], o);
    }

    __shared__ float red[8][36];
    const int wid = tid >> 5, lane = tid & 31;
    if (lane == 0) {
#pragma unroll
        for (int r = 0; r < 4; r++) {
#pragma unroll
            for (int bb = 0; bb < 8; bb++) red[wid][r * 9 + bb] = acc[r][bb];
            red[wid][r * 9 + 8] = l1[r];
        }
    }
    __syncthreads();
    if (tid < 36) {
        float s = 0.f;
#pragma unroll
        for (int w8 = 0; w8 < 8; w8++) s += red[w8][tid];
        g_part[(sp * 128 + rb) * 36 + tid] = s;
    }
}

// -------- kernel 4b: combine partials + normalize + write output --------
__global__ void __launch_bounds__(64)
k_fin2(float* __restrict__ out) {
    const int rb  = blockIdx.x;          // 0..127
    const int tid = threadIdx.x;
    __shared__ float tot[36];
    if (tid < 36) {
        float s = 0.f;
#pragma unroll
        for (int sp = 0; sp < 4; sp++) s += g_part[(sp * 128 + rb) * 36 + tid];
        tot[tid] = s;
    }
    __syncthreads();
    if (tid < 32) {
        int r  = tid >> 3;
        int bb = tid & 7;
        float l = tot[r * 9 + 8];
        out[bb * NC + (rb * 4 + r)] = tot[r * 9 + bb] / fmaxf(l, 1e-12f);
    }
}

// -------- launcher --------
extern "C" void kernel_launch(void* const* d_in, const int* in_sizes, int n_in,
                              void* d_out, int out_size) {
    const int*   doc_index = (const int*)d_in[0];
    const float* attn      = (const float*)d_in[1];
    const float* emb       = (const float*)d_in[2];
    const float* vvt       = (const float*)d_in[3];
    const float* phi       = (const float*)d_in[4];
    const float* diff      = (const float*)d_in[5];
    const float* start     = (const float*)d_in[6];
    float* out = (float*)d_out;

    k_prepA<<<(NB * ND * K1 + 511) / 512, 512>>>(doc_index, emb, diff, start);
    k_prepB<<<NVP / 128, 256>>>(vvt);

    cudaFuncSetAttribute(k_main, cudaFuncAttributeMaxDynamicSharedMemorySize, SMEM_MAIN);
    dim3 grid(N_VT, NB * 4);
    k_main<<<grid, 256, SMEM_MAIN>>>(attn);

    k_fold<<<(8 * NVP + 255) / 256, 256>>>();

    dim3 g1(128, 4);
    k_fin1<<<g1, 256>>>(phi);
    k_fin2<<<128, 64>>>(out);
}

// round 17
// speedup vs baseline: 1.0300x; 1.0070x over previous
#include <cuda_runtime.h>
#include <cuda_fp16.h>
#include <cstdint>

#define NB   8
#define ND   1024
#define DD   100
#define NV   30000
#define NC   512

#define K1   112              // 100 + 12 zero pad (7 x k16)
#define NVP  30208            // 118 * 256
#define TILE_N 256
#define TILE_M 64
#define N_VT (NVP / TILE_N)   // 118
#define NDC  4                // 4 chunks of 64 rows = 256 rows per CTA

#define PITCH 240             // 15 x 16B, odd units -> conflict-free ldmatrix
#define ABUF  (TILE_M * PITCH)               // 15360
#define BBUF  (TILE_N * PITCH)               // 61440
#define NSTAGE 3
#define VRED_OFF  (BBUF + NSTAGE * ABUF)             // 107520
#define MBAR_OFF  (VRED_OFF + 8 * 64 * 4)            // 109568 (ready[3], free[3])
#define SMEM_MAIN (MBAR_OFF + 64)                    // 109632

#define INV_STEP (14.0f / 1.49f)

// -------- device scratch --------
__device__ __half g_A[(size_t)NB * ND * K1];     // [row][k] row-major, 224B rows
__device__ __half g_B[(size_t)NVP * K1];         // [v][k]
__device__ float g_w8[8 * NVP];                  // accumulated over mc via REDG
__device__ float g_binw[16];
__device__ float g_part[4 * 128 * 36];

// -------- helpers --------
__device__ __forceinline__ uint32_t smem_u32(const void* p) {
    return (uint32_t)__cvta_generic_to_shared(p);
}
__device__ __forceinline__ void cpa16(uint32_t dst, const void* src) {
    asm volatile("cp.async.cg.shared.global [%0], [%1], 16;" :: "r"(dst), "l"(src));
}
__device__ __forceinline__ void cpa_mbar_arrive_noinc(uint32_t mbar) {
    asm volatile("cp.async.mbarrier.arrive.noinc.shared.b64 [%0];" :: "r"(mbar) : "memory");
}
__device__ __forceinline__ void mbar_init(uint32_t mbar, uint32_t cnt) {
    asm volatile("mbarrier.init.shared.b64 [%0], %1;" :: "r"(mbar), "r"(cnt) : "memory");
}
__device__ __forceinline__ void mbar_arrive(uint32_t mbar) {
    asm volatile("mbarrier.arrive.shared.b64 _, [%0];" :: "r"(mbar) : "memory");
}
__device__ __forceinline__ void mbar_wait(uint32_t mbar, uint32_t parity) {
    asm volatile(
        "{\n\t.reg .pred P1;\n\t"
        "WAIT_%=:\n\t"
        "mbarrier.try_wait.parity.acquire.cta.shared::cta.b64 P1, [%0], %1, 0x989680;\n\t"
        "@P1 bra.uni DONE_%=;\n\t"
        "bra.uni WAIT_%=;\n\t"
        "DONE_%=:\n\t}"
        :: "r"(mbar), "r"(parity) : "memory");
}

__device__ __forceinline__ void ldm4(uint32_t& r0, uint32_t& r1, uint32_t& r2, uint32_t& r3,
                                     uint32_t addr) {
    asm volatile("ldmatrix.sync.aligned.m8n8.x4.shared.b16 {%0,%1,%2,%3}, [%4];"
                 : "=r"(r0), "=r"(r1), "=r"(r2), "=r"(r3) : "r"(addr));
}
// f16 x f16 inputs -> f32 accumulators
__device__ __forceinline__ void mma16816(float* c, const uint32_t* a, const uint32_t* b) {
    asm volatile(
        "mma.sync.aligned.m16n8k16.row.col.f32.f16.f16.f32 "
        "{%0,%1,%2,%3}, {%4,%5,%6,%7}, {%8,%9}, {%0,%1,%2,%3};"
        : "+f"(c[0]), "+f"(c[1]), "+f"(c[2]), "+f"(c[3])
        : "r"(a[0]), "r"(a[1]), "r"(a[2]), "r"(a[3]), "r"(b[0]), "r"(b[1]));
}
// init form: c = zero register (kills per-dc accumulator-zeroing MOVs)
__device__ __forceinline__ void mma16816_init(float* d, const uint32_t* a, const uint32_t* b,
                                              float z) {
    asm volatile(
        "mma.sync.aligned.m16n8k16.row.col.f32.f16.f16.f32 "
        "{%0,%1,%2,%3}, {%4,%5,%6,%7}, {%8,%9}, {%10,%10,%10,%10};"
        : "=f"(d[0]), "=f"(d[1]), "=f"(d[2]), "=f"(d[3])
        : "r"(a[0]), "r"(a[1]), "r"(a[2]), "r"(a[3]), "r"(b[0]), "r"(b[1]), "f"(z));
}
__device__ __forceinline__ float fma_sat(float a, float b, float c) {
    float d;
    asm("fma.rn.sat.f32 %0, %1, %2, %3;" : "=f"(d) : "f"(a), "f"(b), "f"(c));
    return d;
}
// shfl.idx taking raw bits as lane index (b[4:0] used; magic guarantees low bits = dig)
__device__ __forceinline__ float shfl_idx_raw(float v, uint32_t idx) {
    float r;
    asm volatile("shfl.sync.idx.b32 %0, %1, %2, 0x1f, 0xffffffff;"
                 : "=f"(r) : "f"(v), "r"(idx));
    return r;
}

// -------- kernel 1: fused prep (binw + A gather/cast + B transpose/cast + zero g_w8) ----
#define PREPA_BLOCKS ((NB * ND * K1) / 256)   // 3584
#define PREPB_BLOCKS (NVP / 128)              // 236
__global__ void __launch_bounds__(256)
k_prep(const int* __restrict__ doc_index, const float* __restrict__ emb,
       const float* __restrict__ Vv_T,
       const float* __restrict__ diff, const float* __restrict__ start) {
    __shared__ __half stage[128 * 120];
    const int bx = blockIdx.x;
    const int tid = threadIdx.x;

    if (bx < PREPA_BLOCKS) {
        if (bx == 0 && tid == 0) {
            float acc = start[0];
            for (int j = 0; j < 16; j++) {
                float d = diff[j];
                acc += d > 0.f ? d : 0.f;
                g_binw[j] = acc;
            }
        }
        int e = bx * 256 + tid;           // exact multiple of total, no bound check
        if (e < 8 * NVP) g_w8[e] = 0.f;   // zero the accumulation buffer
        int r = e / K1;
        int k = e - r * K1;
        float val = (k < DD) ? emb[(size_t)doc_index[r] * DD + k] : 0.f;
        g_A[e] = __float2half(val);
    } else {
        const int v0 = (bx - PREPA_BLOCKS) * 128;
        for (int idx = tid; idx < DD * 128; idx += 256) {
            int k = idx >> 7, c = idx & 127;
            int v = v0 + c;
            float val = (v < NV) ? Vv_T[(size_t)k * NV + v] : 0.f;
            stage[c * 120 + k] = __float2half(val);
        }
        for (int idx = tid; idx < 128 * 12; idx += 256) {
            int c = idx / 12, u = idx - c * 12;
            stage[c * 120 + DD + u] = __float2half(0.f);
        }
        __syncthreads();
        const uint32_t* sg = (const uint32_t*)stage;
        uint32_t* dst = (uint32_t*)g_B;
        for (int e = tid; e < 128 * 56; e += 256) {
            int row = e / 56, u = e - row * 56;
            dst[(size_t)(v0 + row) * 56 + u] = sg[row * 60 + u];
        }
    }
}

// -------- kernel 3: f16-input tensor GEMM + digitize + attn-weighted d-reduction --------
// grid (118, 32): blockIdx.y = b*4 + mc; 256 threads = 8 warps 2(M) x 4(N); warp tile 32x64.
// 2 CTAs / SM; 3-stage A ring with noinc-mbarrier producer/consumer.  [converged design]
// mc partial sums combined directly via atomicAdd (REDG) into g_w8 — no fold kernel.
__device__ __forceinline__ void load_a_chunk(int rowbase, int dc, uint32_t dbase, int tid) {
    const char* base = (const char*)g_A + ((size_t)(rowbase + dc * TILE_M)) * (K1 * 2);
#pragma unroll 1
    for (int i = tid; i < TILE_M * 14; i += 256) {
        int row = i / 14, u = i - row * 14;
        cpa16(dbase + row * PITCH + u * 16, base + (size_t)row * (K1 * 2) + u * 16);
    }
}

__global__ void __launch_bounds__(256, 2)
k_main(const float* __restrict__ attn) {
    extern __shared__ unsigned char sm[];
    const uint32_t sBs = smem_u32(sm);
    const uint32_t sAs = sBs + BBUF;
    float* vred = (float*)(sm + VRED_OFF);
    const uint32_t mb_ready = sBs + MBAR_OFF;        // 3 x 8B
    const uint32_t mb_free  = sBs + MBAR_OFF + 24;   // 3 x 8B

    const int tid  = threadIdx.x;
    const int lane = tid & 31, wid = tid >> 5;
    const int wm   = wid >> 2, wn = wid & 3;      // 2 x 4 warps
    const int by   = blockIdx.y;
    const int b    = by >> 2;
    const int mc   = by & 3;
    const int rowbase = b * ND + mc * 256;
    const int v0   = blockIdx.x * TILE_N;

    const float binw_r = __ldg(&g_binw[lane & 15]);
    const int lm_row  = lane & 15;
    const int lm_koff = (lane >> 4) << 3;

    // digitize: y = sat(s*S2 + C2), m = rn(y*15 + 2^23), bits[4:0] = dig
    const float S2 = INV_STEP / 15.0f;
    const float C2 = (0.5f * INV_STEP + 0.5f) / 15.0f;
    const float MAGIC = 8388608.0f;   // 2^23
    const float FZERO = 0.0f;

    // ---- init mbarriers, then make visible ----
    if (tid == 0) {
#pragma unroll
        for (int s = 0; s < 3; s++) {
            mbar_init(mb_ready + s * 8, 256);
            mbar_init(mb_free  + s * 8, 8);
        }
    }
    __syncthreads();

    // ---- prologue: B + A0 -> ready[0]; A1 -> ready[1] ----
    {
        const char* bsrc = (const char*)g_B + (size_t)v0 * (K1 * 2);
#pragma unroll 1
        for (int i = tid; i < TILE_N * 14; i += 256) {
            int row = i / 14, u = i - row * 14;
            cpa16(sBs + row * PITCH + u * 16, bsrc + (size_t)row * (K1 * 2) + u * 16);
        }
        load_a_chunk(rowbase, 0, sAs, tid);
        cpa_mbar_arrive_noinc(mb_ready + 0 * 8);     // B + A0 tracked
        load_a_chunk(rowbase, 1, sAs + ABUF, tid);
        cpa_mbar_arrive_noinc(mb_ready + 1 * 8);
    }

    float vcol[16];
#pragma unroll
    for (int j = 0; j < 16; j++) vcol[j] = 0.f;

    const float* attn_b = attn + rowbase;

#pragma unroll 1
    for (int dc = 0; dc < NDC; ++dc) {
        const int slot = dc % NSTAGE;

        // 1. wait A[dc] (and B, folded into ready[0]) ready
        mbar_wait(mb_ready + slot * 8, (uint32_t)((dc / 3) & 1));

        // 2. prefetch A[dc+2] into slot (dc+2)%3 (wait for its readers first)
        if (dc + 2 < NDC) {
            const int ps = (dc + 2) % NSTAGE;
            if (dc >= 1)
                mbar_wait(mb_free + ps * 8, (uint32_t)(((dc - 1) / 3) & 1));
            load_a_chunk(rowbase, dc + 2, sAs + (uint32_t)ps * ABUF, tid);
            cpa_mbar_arrive_noinc(mb_ready + ps * 8);
        }

        const uint32_t sA = sAs + (uint32_t)slot * ABUF;

        // prefetch the 4 attn values used in this dc's epilogue
        const int arow = dc * TILE_M + wm * 32 + (lane >> 2);
        float av[2][2];
#pragma unroll
        for (int mi = 0; mi < 2; mi++)
#pragma unroll
            for (int gg = 0; gg < 2; gg++)
                av[mi][gg] = __ldg(&attn_b[arow + mi * 16 + gg * 8]);

        float acc[2][8][4];

        // ---- 3. 7 x k16 MMA steps (ks=0 uses zero-input form: no acc zeroing) ----
#pragma unroll
        for (int ks = 0; ks < K1 / 16; ks++) {
            const int kl = ks * 16;
            uint32_t a[2][4];
#pragma unroll
            for (int mi = 0; mi < 2; mi++) {
                uint32_t addr = sA + (wm * 32 + mi * 16 + lm_row) * PITCH
                              + (kl + lm_koff) * 2;
                ldm4(a[mi][0], a[mi][1], a[mi][2], a[mi][3], addr);
            }
            uint32_t bf[8][2];
#pragma unroll
            for (int nb = 0; nb < 4; nb++) {
                uint32_t addr = sBs + (wn * 64 + nb * 16 + lm_row) * PITCH
                              + (kl + lm_koff) * 2;
                uint32_t r0, r1, r2, r3;
                ldm4(r0, r1, r2, r3, addr);
                bf[nb * 2][0] = r0;     bf[nb * 2][1] = r2;
                bf[nb * 2 + 1][0] = r1; bf[nb * 2 + 1][1] = r3;
            }
            if (ks == 0) {
#pragma unroll
                for (int mi = 0; mi < 2; mi++)
#pragma unroll
                    for (int nj = 0; nj < 8; nj++)
                        mma16816_init(acc[mi][nj], a[mi], bf[nj], FZERO);
            } else {
#pragma unroll
                for (int mi = 0; mi < 2; mi++)
#pragma unroll
                    for (int nj = 0; nj < 8; nj++)
                        mma16816(acc[mi][nj], a[mi], bf[nj]);
            }
        }

        // 4. this warp is done reading A stage 'slot'
        if (lane == 0) mbar_arrive(mb_free + slot * 8);

        // ---- 5. epilogue: sat-fma, magic-fma, shfl(raw), fma ----
#pragma unroll
        for (int mi = 0; mi < 2; mi++) {
#pragma unroll
            for (int gg = 0; gg < 2; gg++) {
                const float a_v = av[mi][gg];
#pragma unroll
                for (int nj = 0; nj < 8; nj++) {
#pragma unroll
                    for (int cc = 0; cc < 2; cc++) {
                        float s = acc[mi][nj][gg * 2 + cc];
                        float y = fma_sat(s, S2, C2);
                        float m = fmaf(y, 15.0f, MAGIC);
                        float w = shfl_idx_raw(binw_r, __float_as_uint(m));
                        vcol[nj * 2 + cc] = fmaf(a_v, w, vcol[nj * 2 + cc]);
                    }
                }
            }
        }
    }

    // ---- reduce vcol over lanes sharing the same columns ----
#pragma unroll
    for (int j = 0; j < 16; j++) {
        vcol[j] += __shfl_down_sync(0xffffffffu, vcol[j], 16);
        vcol[j] += __shfl_down_sync(0xffffffffu, vcol[j], 8);
        vcol[j] += __shfl_down_sync(0xffffffffu, vcol[j], 4);
    }
    if (lane < 4) {
#pragma unroll
        for (int j = 0; j < 16; j++) {
            int nj = j >> 1, cc = j & 1;
            vred[wid * 64 + nj * 8 + lane * 2 + cc] = vcol[j];
        }
    }
    __syncthreads();
    {
        int wn2 = tid >> 6, cl = tid & 63;
        float s = vred[wn2 * 64 + cl] + vred[(4 + wn2) * 64 + cl];
        atomicAdd(&g_w8[(size_t)b * NVP + v0 + tid], s);   // REDG: mc combine
    }
}

// -------- kernel 4a: phi L1 + partial dots; 4 rows/block, 4 NV-chunks, unroll-2 MLP --------
// grid (128 rb, 4 sp): ~7.4 main-loop iterations per block.
#define CHV 7552   // NVP/4
__global__ void __launch_bounds__(256)
k_fin1(const float* __restrict__ phi) {
    const int rb  = blockIdx.x;          // 0..127 (4 concept rows each)
    const int sp  = blockIdx.y;          // 0..3   (NV chunk)
    const int n0  = rb * 4;
    const int tid = threadIdx.x;

    const int vbeg = sp * CHV;
    const int vend = (vbeg + CHV < NV) ? vbeg + CHV : NV;

    float acc[4][8];
    float l1[4];
#pragma unroll
    for (int r = 0; r < 4; r++) {
        l1[r] = 0.f;
#pragma unroll
        for (int bb = 0; bb < 8; bb++) acc[r][bb] = 0.f;
    }

#pragma unroll 2
    for (int base = vbeg + tid * 4; base < vend; base += 1024) {
        float4 w[8];
#pragma unroll
        for (int bb = 0; bb < 8; bb++)
            w[bb] = *(const float4*)&g_w8[(size_t)bb * NVP + base];
#pragma unroll
        for (int r = 0; r < 4; r++) {
            float4 p = *(const float4*)&phi[(size_t)(n0 + r) * NV + base];
            l1[r] += fabsf(p.x) + fabsf(p.y) + fabsf(p.z) + fabsf(p.w);
#pragma unroll
            for (int bb = 0; bb < 8; bb++)
                acc[r][bb] += p.x * w[bb].x + p.y * w[bb].y + p.z * w[bb].z + p.w * w[bb].w;
        }
    }

    const unsigned mask = 0xffffffffu;
#pragma unroll
    for (int r = 0; r < 4; r++) {
#pragma unroll
        for (int bb = 0; bb < 8; bb++)
#pragma unroll
            for (int o = 16; o > 0; o >>= 1)
                acc[r][bb] += __shfl_down_sync(mask, acc[r][bb], o);
#pragma unroll
        for (int o = 16; o > 0; o >>= 1)
            l1[r] += __shfl_down_sync(mask, l1[r], o);
    }

    __shared__ float red[8][36];
    const int wid = tid >> 5, lane = tid & 31;
    if (lane == 0) {
#pragma unroll
        for (int r = 0; r < 4; r++) {
#pragma unroll
            for (int bb = 0; bb < 8; bb++) red[wid][r * 9 + bb] = acc[r][bb];
            red[wid][r * 9 + 8] = l1[r];
        }
    }
    __syncthreads();
    if (tid < 36) {
        float s = 0.f;
#pragma unroll
        for (int w8 = 0; w8 < 8; w8++) s += red[w8][tid];
        g_part[(sp * 128 + rb) * 36 + tid] = s;
    }
}

// -------- kernel 4b: combine partials + normalize + write output --------
__global__ void __launch_bounds__(64)
k_fin2(float* __restrict__ out) {
    const int rb  = blockIdx.x;          // 0..127
    const int tid = threadIdx.x;
    __shared__ float tot[36];
    if (tid < 36) {
        float s = 0.f;
#pragma unroll
        for (int sp = 0; sp < 4; sp++) s += g_part[(sp * 128 + rb) * 36 + tid];
        tot[tid] = s;
    }
    __syncthreads();
    if (tid < 32) {
        int r  = tid >> 3;
        int bb = tid & 7;
        float l = tot[r * 9 + 8];
        out[bb * NC + (rb * 4 + r)] = tot[r * 9 + bb] / fmaxf(l, 1e-12f);
    }
}

// -------- launcher --------
extern "C" void kernel_launch(void* const* d_in, const int* in_sizes, int n_in,
                              void* d_out, int out_size) {
    const int*   doc_index = (const int*)d_in[0];
    const float* attn      = (const float*)d_in[1];
    const float* emb       = (const float*)d_in[2];
    const float* vvt       = (const float*)d_in[3];
    const float* phi       = (const float*)d_in[4];
    const float* diff      = (const float*)d_in[5];
    const float* start     = (const float*)d_in[6];
    float* out = (float*)d_out;

    k_prep<<<PREPA_BLOCKS + PREPB_BLOCKS, 256>>>(doc_index, emb, vvt, diff, start);

    cudaFuncSetAttribute(k_main, cudaFuncAttributeMaxDynamicSharedMemorySize, SMEM_MAIN);
    dim3 grid(N_VT, NB * 4);
    k_main<<<grid, 256, SMEM_MAIN>>>(attn);

    dim3 g1(128, 4);
    k_fin1<<<g1, 256>>>(phi);
    k_fin2<<<128, 64>>>(out);
}